// round 14
// baseline (speedup 1.0000x reference)
#include <cuda_runtime.h>
#include <cuda_fp16.h>
#include <cstdint>
#include <math.h>

// Problem constants
#define IC    32         // in capsules
#define DDIM  288        // ich*w*h
#define OC    10         // out capsules
#define CH    16         // out channels
#define BSZ   64         // batch
#define JDIM  160        // OC*CH
#define NT    10240      // BSZ*OC*CH
// cluster route config: 16 CTAs x 640 threads == NT
#define CLN   16
#define CTPB  640
// fallback spin route config
#define RBLK  40
#define RTPB  256

// Scratch (device globals: no allocation allowed)
__device__ __half2 g_usum_h[IC * NT];             // packed d-halves: (.x=dh0, .y=dh1)
__device__ float g_udot_p[2][IC * OC];            // d-half partials of u_dot (fp32)
__device__ __align__(128) float g_part[3][RBLK];  // partials (fallback path only)
__device__ volatile unsigned g_flag[RBLK];        // spin-barrier epochs (fallback)

// ---------------------------------------------------------------------------
// K1: partial GEMM (R12-exact tiling: 640 blocks x 128 threads, 64b x 16j x
// 144d FFMA tile). Stores u_sum partial as the dh-th half of a __half2.
// ---------------------------------------------------------------------------
__global__ __launch_bounds__(128) void k1_gemm(const float* __restrict__ u,
                                               const float* __restrict__ W) {
    const int bid = blockIdx.x;
    const int dh  = bid & 1;
    const int o   = (bid >> 1) % 10;
    const int i   = bid / 20;
    const int j0  = o * 16;
    const int tid = threadIdx.x;
    const int tx  = tid & 7;
    const int ty  = tid >> 3;

    __shared__ float u_t[16][68];
    __shared__ float w_s[16][16];
    __shared__ float redw[4];

    float acc[4][2] = {};

    const float* ug = u + i * DDIM + dh * 144;
    const float* wg = W + (size_t)i * DDIM * JDIM + (size_t)(dh * 144) * JDIM + j0;

    float upf[8], wpf[2];
#pragma unroll
    for (int p = 0; p < 8; p++) { int e = tid + p * 128; upf[p] = ug[(e >> 4) * (IC * DDIM) + (e & 15)]; }
#pragma unroll
    for (int p = 0; p < 2; p++) { int e = tid + p * 128; wpf[p] = wg[(e >> 4) * JDIM + (e & 15)]; }

    for (int c = 0; c < 9; c++) {
        __syncthreads();
#pragma unroll
        for (int p = 0; p < 8; p++) { int e = tid + p * 128; u_t[e & 15][e >> 4] = upf[p]; }
#pragma unroll
        for (int p = 0; p < 2; p++) { int e = tid + p * 128; w_s[e >> 4][e & 15] = wpf[p]; }
        __syncthreads();
        if (c < 8) {
            const int d0 = (c + 1) * 16;
#pragma unroll
            for (int p = 0; p < 8; p++) { int e = tid + p * 128; upf[p] = ug[(e >> 4) * (IC * DDIM) + d0 + (e & 15)]; }
#pragma unroll
            for (int p = 0; p < 2; p++) { int e = tid + p * 128; wpf[p] = wg[(d0 + (e >> 4)) * JDIM + (e & 15)]; }
        }
#pragma unroll
        for (int dd = 0; dd < 16; dd++) {
            float4 uv = *(const float4*)&u_t[dd][ty * 4];
            float2 wv = *(const float2*)&w_s[dd][tx * 2];
            acc[0][0] = fmaf(uv.x, wv.x, acc[0][0]); acc[0][1] = fmaf(uv.x, wv.y, acc[0][1]);
            acc[1][0] = fmaf(uv.y, wv.x, acc[1][0]); acc[1][1] = fmaf(uv.y, wv.y, acc[1][1]);
            acc[2][0] = fmaf(uv.z, wv.x, acc[2][0]); acc[2][1] = fmaf(uv.z, wv.y, acc[2][1]);
            acc[3][0] = fmaf(uv.w, wv.x, acc[3][0]); acc[3][1] = fmaf(uv.w, wv.y, acc[3][1]);
        }
    }

    // store partial as fp16 half of packed word; per-thread fp32 sum for u_dot
    float lsum = 0.f;
    __half* dsth = (__half*)g_usum_h + ((size_t)i * NT + o * 1024) * 2 + dh;
#pragma unroll
    for (int bb = 0; bb < 4; bb++) {
#pragma unroll
        for (int jj = 0; jj < 2; jj++) {
            int b = ty * 4 + bb, ch = tx * 2 + jj;
            dsth[(b * CH + ch) * 2] = __float2half(acc[bb][jj]);
            lsum += acc[bb][jj];
        }
    }
#pragma unroll
    for (int off = 16; off > 0; off >>= 1) lsum += __shfl_xor_sync(0xffffffffu, lsum, off);
    if ((tid & 31) == 0) redw[tid >> 5] = lsum;
    __syncthreads();
    if (tid == 0) g_udot_p[dh][i * OC + o] = (redw[0] + redw[1]) + (redw[2] + redw[3]);
}

// ---------------------------------------------------------------------------
__device__ __forceinline__ float warp_sum_f(float v) {
#pragma unroll
    for (int o = 16; o > 0; o >>= 1) v += __shfl_xor_sync(0xffffffffu, v, o);
    return v;
}
__device__ __forceinline__ float warp_max_f(float v) {
#pragma unroll
    for (int o = 16; o > 0; o >>= 1) v = fmaxf(v, __shfl_xor_sync(0xffffffffu, v, o));
    return v;
}

// ===========================================================================
// Cluster route: 16 CTAs x 640 threads; warp-local coupling + shfl sweep;
// DSMEM partial exchange; split arrive/wait to hide xd/S1 in phase 1.
// ===========================================================================
__device__ __forceinline__ unsigned int smem_u32(const void* p) {
    unsigned int a;
    asm("{ .reg .u64 t; cvta.to.shared.u64 t, %1; cvt.u32.u64 %0, t; }"
        : "=r"(a) : "l"(p));
    return a;
}

__device__ __forceinline__ void cluster_arrive_all() {
    asm volatile("barrier.cluster.arrive.aligned;" ::: "memory");
}
__device__ __forceinline__ void cluster_wait_all() {
    asm volatile("barrier.cluster.wait.aligned;" ::: "memory");
}

__device__ __forceinline__ void dsmem_store_rank(unsigned int laddr, int rank, float val) {
    asm volatile(
        "{ .reg .b32 ra; mapa.shared::cluster.u32 ra, %0, %1; "
        "st.shared::cluster.f32 [ra], %2; }"
        :: "r"(laddr), "r"(rank), "f"(val) : "memory");
}

__global__ __launch_bounds__(CTPB, 1) __cluster_dims__(CLN, 1, 1)
void k_route_c(float* __restrict__ out) {
    __shared__ float redw[CTPB / 32];
    __shared__ float part_s[3][CLN];
    const int tid  = threadIdx.x;
    const int lane = tid & 31;
    const int w    = tid >> 5;
    const int t    = blockIdx.x * CTPB + tid;
    const int o    = t >> 10;            // warp-uniform

    // ---- prologue: x[i] from packed half2 (one LDG per i) ----
    float x[IC];
#pragma unroll
    for (int i = 0; i < IC; i++) {
        __half2 h = __ldcg(&g_usum_h[i * NT + t]);
        float2 f = __half22float2(h);
        x[i] = f.x + f.y;
    }

    // publish phase-1 partial
    float s1 = 0.f;
#pragma unroll
    for (int i = 0; i < IC; i++) s1 += x[i];
    s1 *= (1.f / 32.f);
    {
        float ws = warp_sum_f(fabsf(s1));
        if (lane == 0) redw[w] = ws;
        __syncthreads();
        if (w == 0) {
            float a = warp_sum_f((lane < CTPB / 32) ? redw[lane] : 0.f);
            if (lane < CLN)
                dsmem_store_rank(smem_u32(&part_s[0][blockIdx.x]), lane, a);
        }
        cluster_arrive_all();
    }
    // hidden behind the barrier: xd load + phase-invariant S1
    float xd = __ldcg(&g_udot_p[0][lane * OC + o]) + __ldcg(&g_udot_p[1][lane * OC + o]);
    const float S1 = warp_sum_f(xd) * (1.f / 32.f);
    cluster_wait_all();

#define PHASE_PART(v, it)                                                     \
    {                                                                         \
        float ws = warp_sum_f(fabsf(v));                                      \
        if (lane == 0) redw[w] = ws;                                          \
        __syncthreads();                                                      \
        if (w == 0) {                                                         \
            float a = warp_sum_f((lane < CTPB / 32) ? redw[lane] : 0.f);      \
            if (lane < CLN)                                                   \
                dsmem_store_rank(smem_u32(&part_s[it][blockIdx.x]), lane, a); \
        }                                                                     \
        cluster_arrive_all();                                                 \
        cluster_wait_all();                                                   \
    }
#define READ_NORM(it)  warp_sum_f((lane < CLN) ? part_s[it][lane] : 0.f)

    // ---- phase 2: c2 = softmax_i(xd*g2), g2 = f1*S1 (shift-free, tiny logits)
    float n1 = READ_NORM(0);
    float f1 = n1 / (1.f + n1 * n1);
    float g2 = f1 * S1;
    float e2 = __expf(xd * g2);
    float c2 = e2 * (1.f / warp_sum_f(e2));
    float S2 = warp_sum_f(c2 * xd);
    float s2 = 0.f;
#pragma unroll
    for (int i = 0; i < IC; i++)
        s2 = fmaf(__shfl_sync(0xffffffffu, c2, i), x[i], s2);
    PHASE_PART(s2, 1);

    // ---- phase 3: c3 = softmax_i(xd*(g2 + f2*S2)) ----
    float n2 = READ_NORM(1);
    float f2 = n2 / (1.f + n2 * n2);
    float g3 = g2 + f2 * S2;
    float e3 = __expf(xd * g3);
    float c3 = e3 * (1.f / warp_sum_f(e3));
    float s3 = 0.f;
#pragma unroll
    for (int i = 0; i < IC; i++)
        s3 = fmaf(__shfl_sync(0xffffffffu, c3, i), x[i], s3);
    PHASE_PART(s3, 2);

    // ---- epilogue: squash scale + output ----
    float n3 = READ_NORM(2);
    float fsh = n3 / (1.f + n3 * n3);
    int b = (t >> 4) & 63, ch = t & 15;
    out[(b * OC + o) * CH + ch] = s3 * fsh;
#undef PHASE_PART
#undef READ_NORM
}

// ===========================================================================
// Fallback spin route (flag-array barrier), packed-half2 x.
// ===========================================================================
__device__ __forceinline__ float coupling_val(float xd, float n1, float n2, int iter) {
    float f1 = n1 / (1.f + n1 * n1);
    float S1 = warp_sum_f(xd) * (1.f / 32.f);
    float g = f1 * S1;
    if (iter == 3) {
        float bx = xd * g;
        float m = warp_max_f(bx);
        float e = expf(bx - m);
        float Z = warp_sum_f(e);
        float c2 = e / Z;
        float S2 = warp_sum_f(c2 * xd);
        float f2 = n2 / (1.f + n2 * n2);
        g = g + f2 * S2;
    }
    float bx = xd * g;
    float m = warp_max_f(bx);
    float e = expf(bx - m);
    float Z = warp_sum_f(e);
    return e / Z;
}

__device__ __forceinline__ void gbar(unsigned target) {
    __syncthreads();
    if (threadIdx.x < 32) {
        const int lane = threadIdx.x;
        if (lane == 0) {
            __threadfence();
            g_flag[blockIdx.x] = target;
        }
        bool done;
        do {
            unsigned f0 = g_flag[lane];
            unsigned f1 = (lane < RBLK - 32) ? g_flag[lane + 32] : target;
            done = __all_sync(0xffffffffu, (f0 == target) && (f1 == target));
        } while (!done);
        __threadfence();
    }
    __syncthreads();
}

__device__ __forceinline__ void block_part_s(float v, float* redw, int it) {
    float ws = warp_sum_f(fabsf(v));
    if ((threadIdx.x & 31) == 0) redw[threadIdx.x >> 5] = ws;
    __syncthreads();
    if (threadIdx.x == 0) {
        float a = 0.f;
#pragma unroll
        for (int k = 0; k < RTPB / 32; k++) a += redw[k];
        g_part[it][blockIdx.x] = a;
    }
}

__device__ __forceinline__ float read_norm_s(int it) {
    const int lane = threadIdx.x & 31;
    float n = __ldcg(&g_part[it][lane]);
    n += (lane < RBLK - 32) ? __ldcg(&g_part[it][lane + 32]) : 0.f;
    return warp_sum_f(n);
}

__global__ __launch_bounds__(RTPB) void k_route_spin(float* __restrict__ out) {
    __shared__ float ud[IC * OC];
    __shared__ float cc[IC * OC];
    __shared__ float redw[RTPB / 32];
    __shared__ unsigned ep_s;
    const int tid  = threadIdx.x;
    const int lane = tid & 31;
    const int w    = tid >> 5;
    const int t    = blockIdx.x * RTPB + tid;
    const int o    = t >> 10;

    if (tid == 0) ep_s = g_flag[blockIdx.x];

    for (int k = tid; k < IC * OC; k += RTPB)
        ud[k] = __ldcg(&g_udot_p[0][k]) + __ldcg(&g_udot_p[1][k]);

    float x[IC];
#pragma unroll
    for (int i = 0; i < IC; i++) {
        __half2 h = __ldcg(&g_usum_h[i * NT + t]);
        float2 f = __half22float2(h);
        x[i] = f.x + f.y;
    }
    __syncthreads();
    const unsigned ep = ep_s;

    float s1 = 0.f;
#pragma unroll
    for (int i = 0; i < IC; i++) s1 += x[i];
    s1 *= (1.f / 32.f);
    block_part_s(s1, redw, 0);
    gbar(ep + 1);

    {
        float n1 = read_norm_s(0);
        for (int oo = w; oo < OC; oo += RTPB / 32)
            cc[lane * OC + oo] = coupling_val(ud[lane * OC + oo], n1, 0.f, 2);
    }
    __syncthreads();
    float s2 = 0.f;
#pragma unroll
    for (int i = 0; i < IC; i++) s2 = fmaf(cc[i * OC + o], x[i], s2);
    block_part_s(s2, redw, 1);
    gbar(ep + 2);

    {
        float n1 = read_norm_s(0);
        float n2 = read_norm_s(1);
        for (int oo = w; oo < OC; oo += RTPB / 32)
            cc[lane * OC + oo] = coupling_val(ud[lane * OC + oo], n1, n2, 3);
    }
    __syncthreads();
    float s3 = 0.f;
#pragma unroll
    for (int i = 0; i < IC; i++) s3 = fmaf(cc[i * OC + o], x[i], s3);
    block_part_s(s3, redw, 2);
    gbar(ep + 3);

    float n3 = read_norm_s(2);
    float fsh = n3 / (1.f + n3 * n3);
    int b = (t >> 4) & 63, ch = t & 15;
    out[(b * OC + o) * CH + ch] = s3 * fsh;
}

// ---------------------------------------------------------------------------
extern "C" void kernel_launch(void* const* d_in, const int* in_sizes, int n_in,
                              void* d_out, int out_size) {
    const float* u = (const float*)d_in[0];   // [64,32,8,6,6]
    const float* W = (const float*)d_in[1];   // [32,8,6,6,10,16]
    float* out = (float*)d_out;               // [64,10,16]
    (void)in_sizes; (void)n_in; (void)out_size;

    k1_gemm<<<640, 128>>>(u, W);

    cudaError_t e = cudaFuncSetAttribute(
        k_route_c, cudaFuncAttributeNonPortableClusterSizeAllowed, 1);
    if (e == cudaSuccess) {
        k_route_c<<<CLN, CTPB>>>(out);
        if (cudaGetLastError() != cudaSuccess)
            k_route_spin<<<RBLK, RTPB>>>(out);
    } else {
        (void)cudaGetLastError();
        k_route_spin<<<RBLK, RTPB>>>(out);
    }
}

// round 15
// speedup vs baseline: 1.0014x; 1.0014x over previous
#include <cuda_runtime.h>
#include <cstdint>
#include <math.h>

// Problem constants
#define IC    32         // in capsules
#define DDIM  288        // ich*w*h
#define OC    10         // out capsules
#define CH    16         // out channels
#define BSZ   64         // batch
#define JDIM  160        // OC*CH
#define NT    10240      // BSZ*OC*CH
// cluster route config: 16 CTAs x 640 threads == NT
#define CLN   16
#define CTPB  640
// fallback spin route config
#define RBLK  40
#define RTPB  256

// Scratch (device globals: no allocation allowed)
__device__ float g_usum_p[2][IC * NT];            // d-half partials, [dh][i][t]
__device__ float g_udot_p[2][IC * OC];            // d-half partials of u_dot
__device__ __align__(128) float g_part[3][RBLK];  // partials (fallback path only)
__device__ volatile unsigned g_flag[RBLK];        // spin-barrier epochs (fallback)

// ---------------------------------------------------------------------------
// K1: partial GEMM (R12-exact: 640 blocks x 128 threads, 64b x 16j x 144d
// FFMA tile, coalesced fp32 stores).
// ---------------------------------------------------------------------------
__global__ __launch_bounds__(128) void k1_gemm(const float* __restrict__ u,
                                               const float* __restrict__ W) {
    const int bid = blockIdx.x;
    const int dh  = bid & 1;
    const int o   = (bid >> 1) % 10;
    const int i   = bid / 20;
    const int j0  = o * 16;
    const int tid = threadIdx.x;
    const int tx  = tid & 7;
    const int ty  = tid >> 3;

    __shared__ float u_t[16][68];
    __shared__ float w_s[16][16];
    __shared__ float redw[4];

    float acc[4][2] = {};

    const float* ug = u + i * DDIM + dh * 144;
    const float* wg = W + (size_t)i * DDIM * JDIM + (size_t)(dh * 144) * JDIM + j0;

    float upf[8], wpf[2];
#pragma unroll
    for (int p = 0; p < 8; p++) { int e = tid + p * 128; upf[p] = ug[(e >> 4) * (IC * DDIM) + (e & 15)]; }
#pragma unroll
    for (int p = 0; p < 2; p++) { int e = tid + p * 128; wpf[p] = wg[(e >> 4) * JDIM + (e & 15)]; }

    for (int c = 0; c < 9; c++) {
        __syncthreads();
#pragma unroll
        for (int p = 0; p < 8; p++) { int e = tid + p * 128; u_t[e & 15][e >> 4] = upf[p]; }
#pragma unroll
        for (int p = 0; p < 2; p++) { int e = tid + p * 128; w_s[e >> 4][e & 15] = wpf[p]; }
        __syncthreads();
        if (c < 8) {
            const int d0 = (c + 1) * 16;
#pragma unroll
            for (int p = 0; p < 8; p++) { int e = tid + p * 128; upf[p] = ug[(e >> 4) * (IC * DDIM) + d0 + (e & 15)]; }
#pragma unroll
            for (int p = 0; p < 2; p++) { int e = tid + p * 128; wpf[p] = wg[(d0 + (e >> 4)) * JDIM + (e & 15)]; }
        }
#pragma unroll
        for (int dd = 0; dd < 16; dd++) {
            float4 uv = *(const float4*)&u_t[dd][ty * 4];
            float2 wv = *(const float2*)&w_s[dd][tx * 2];
            acc[0][0] = fmaf(uv.x, wv.x, acc[0][0]); acc[0][1] = fmaf(uv.x, wv.y, acc[0][1]);
            acc[1][0] = fmaf(uv.y, wv.x, acc[1][0]); acc[1][1] = fmaf(uv.y, wv.y, acc[1][1]);
            acc[2][0] = fmaf(uv.z, wv.x, acc[2][0]); acc[2][1] = fmaf(uv.z, wv.y, acc[2][1]);
            acc[3][0] = fmaf(uv.w, wv.x, acc[3][0]); acc[3][1] = fmaf(uv.w, wv.y, acc[3][1]);
        }
    }

    float lsum = 0.f;
    float* dst = g_usum_p[dh] + (size_t)i * NT + o * 1024;
#pragma unroll
    for (int bb = 0; bb < 4; bb++) {
#pragma unroll
        for (int jj = 0; jj < 2; jj++) {
            int b = ty * 4 + bb, ch = tx * 2 + jj;
            dst[b * CH + ch] = acc[bb][jj];
            lsum += acc[bb][jj];
        }
    }
#pragma unroll
    for (int off = 16; off > 0; off >>= 1) lsum += __shfl_xor_sync(0xffffffffu, lsum, off);
    if ((tid & 31) == 0) redw[tid >> 5] = lsum;
    __syncthreads();
    if (tid == 0) g_udot_p[dh][i * OC + o] = (redw[0] + redw[1]) + (redw[2] + redw[3]);
}

// ---------------------------------------------------------------------------
__device__ __forceinline__ float warp_sum_f(float v) {
#pragma unroll
    for (int o = 16; o > 0; o >>= 1) v += __shfl_xor_sync(0xffffffffu, v, o);
    return v;
}
__device__ __forceinline__ float warp_max_f(float v) {
#pragma unroll
    for (int o = 16; o > 0; o >>= 1) v = fmaxf(v, __shfl_xor_sync(0xffffffffu, v, o));
    return v;
}

// ===========================================================================
// Cluster route: 16 CTAs x 640 threads; warp-local coupling + shfl sweep;
// DSMEM partial exchange; split arrive/wait in phase 1 to hide xd/S1.
// ===========================================================================
__device__ __forceinline__ unsigned int smem_u32(const void* p) {
    unsigned int a;
    asm("{ .reg .u64 t; cvta.to.shared.u64 t, %1; cvt.u32.u64 %0, t; }"
        : "=r"(a) : "l"(p));
    return a;
}

__device__ __forceinline__ void cluster_arrive_all() {
    asm volatile("barrier.cluster.arrive.aligned;" ::: "memory");
}
__device__ __forceinline__ void cluster_wait_all() {
    asm volatile("barrier.cluster.wait.aligned;" ::: "memory");
}

__device__ __forceinline__ void dsmem_store_rank(unsigned int laddr, int rank, float val) {
    asm volatile(
        "{ .reg .b32 ra; mapa.shared::cluster.u32 ra, %0, %1; "
        "st.shared::cluster.f32 [ra], %2; }"
        :: "r"(laddr), "r"(rank), "f"(val) : "memory");
}

__global__ __launch_bounds__(CTPB, 1) __cluster_dims__(CLN, 1, 1)
void k_route_c(float* __restrict__ out) {
    __shared__ float redw[CTPB / 32];
    __shared__ float part_s[3][CLN];
    const int tid  = threadIdx.x;
    const int lane = tid & 31;
    const int w    = tid >> 5;
    const int t    = blockIdx.x * CTPB + tid;
    const int o    = t >> 10;            // warp-uniform

    // ---- prologue: x[i] from two fp32 d-half buffers (64 batched LDG) ----
    float x0[IC], x1[IC];
#pragma unroll
    for (int i = 0; i < IC; i++) x0[i] = __ldcg(&g_usum_p[0][i * NT + t]);
#pragma unroll
    for (int i = 0; i < IC; i++) x1[i] = __ldcg(&g_usum_p[1][i * NT + t]);
    float x[IC];
#pragma unroll
    for (int i = 0; i < IC; i++) x[i] = x0[i] + x1[i];

    // ---- phase 1: publish s1 partial; hide xd load + S1 behind barrier ----
    float s1 = 0.f;
#pragma unroll
    for (int i = 0; i < IC; i++) s1 += x[i];
    s1 *= (1.f / 32.f);
    {
        float ws = warp_sum_f(fabsf(s1));
        if (lane == 0) redw[w] = ws;
        __syncthreads();
        if (w == 0) {
            float a = warp_sum_f((lane < CTPB / 32) ? redw[lane] : 0.f);
            if (lane < CLN)
                dsmem_store_rank(smem_u32(&part_s[0][blockIdx.x]), lane, a);
        }
        cluster_arrive_all();
    }
    float xd = __ldcg(&g_udot_p[0][lane * OC + o]) + __ldcg(&g_udot_p[1][lane * OC + o]);
    const float S1 = warp_sum_f(xd) * (1.f / 32.f);   // phase-invariant
    cluster_wait_all();

#define PHASE_PART(v, it)                                                     \
    {                                                                         \
        float ws = warp_sum_f(fabsf(v));                                      \
        if (lane == 0) redw[w] = ws;                                          \
        __syncthreads();                                                      \
        if (w == 0) {                                                         \
            float a = warp_sum_f((lane < CTPB / 32) ? redw[lane] : 0.f);      \
            if (lane < CLN)                                                   \
                dsmem_store_rank(smem_u32(&part_s[it][blockIdx.x]), lane, a); \
        }                                                                     \
        cluster_arrive_all();                                                 \
        cluster_wait_all();                                                   \
    }
#define READ_NORM(it)  warp_sum_f((lane < CLN) ? part_s[it][lane] : 0.f)

    // ---- phase 2: c2 = softmax_i(xd*g2), g2 = f1*S1 (shift-free, tiny logits)
    float n1 = READ_NORM(0);
    float f1 = n1 / (1.f + n1 * n1);
    float g2 = f1 * S1;
    float e2 = __expf(xd * g2);
    float c2 = e2 * (1.f / warp_sum_f(e2));
    float S2 = warp_sum_f(c2 * xd);
    float s2 = 0.f;
#pragma unroll
    for (int i = 0; i < IC; i++)
        s2 = fmaf(__shfl_sync(0xffffffffu, c2, i), x[i], s2);
    PHASE_PART(s2, 1);

    // ---- phase 3: c3 = softmax_i(xd*(g2 + f2*S2)) ----
    float n2 = READ_NORM(1);
    float f2 = n2 / (1.f + n2 * n2);
    float g3 = g2 + f2 * S2;
    float e3 = __expf(xd * g3);
    float c3 = e3 * (1.f / warp_sum_f(e3));
    float s3 = 0.f;
#pragma unroll
    for (int i = 0; i < IC; i++)
        s3 = fmaf(__shfl_sync(0xffffffffu, c3, i), x[i], s3);
    PHASE_PART(s3, 2);

    // ---- epilogue: squash scale + output ----
    float n3 = READ_NORM(2);
    float fsh = n3 / (1.f + n3 * n3);
    int b = (t >> 4) & 63, ch = t & 15;
    out[(b * OC + o) * CH + ch] = s3 * fsh;
#undef PHASE_PART
#undef READ_NORM
}

// ===========================================================================
// Fallback spin route (flag-array barrier), two fp32 d-half buffers.
// ===========================================================================
__device__ __forceinline__ float coupling_val(float xd, float n1, float n2, int iter) {
    float f1 = n1 / (1.f + n1 * n1);
    float S1 = warp_sum_f(xd) * (1.f / 32.f);
    float g = f1 * S1;
    if (iter == 3) {
        float bx = xd * g;
        float m = warp_max_f(bx);
        float e = expf(bx - m);
        float Z = warp_sum_f(e);
        float c2 = e / Z;
        float S2 = warp_sum_f(c2 * xd);
        float f2 = n2 / (1.f + n2 * n2);
        g = g + f2 * S2;
    }
    float bx = xd * g;
    float m = warp_max_f(bx);
    float e = expf(bx - m);
    float Z = warp_sum_f(e);
    return e / Z;
}

__device__ __forceinline__ void gbar(unsigned target) {
    __syncthreads();
    if (threadIdx.x < 32) {
        const int lane = threadIdx.x;
        if (lane == 0) {
            __threadfence();
            g_flag[blockIdx.x] = target;
        }
        bool done;
        do {
            unsigned f0 = g_flag[lane];
            unsigned f1 = (lane < RBLK - 32) ? g_flag[lane + 32] : target;
            done = __all_sync(0xffffffffu, (f0 == target) && (f1 == target));
        } while (!done);
        __threadfence();
    }
    __syncthreads();
}

__device__ __forceinline__ void block_part_s(float v, float* redw, int it) {
    float ws = warp_sum_f(fabsf(v));
    if ((threadIdx.x & 31) == 0) redw[threadIdx.x >> 5] = ws;
    __syncthreads();
    if (threadIdx.x == 0) {
        float a = 0.f;
#pragma unroll
        for (int k = 0; k < RTPB / 32; k++) a += redw[k];
        g_part[it][blockIdx.x] = a;
    }
}

__device__ __forceinline__ float read_norm_s(int it) {
    const int lane = threadIdx.x & 31;
    float n = __ldcg(&g_part[it][lane]);
    n += (lane < RBLK - 32) ? __ldcg(&g_part[it][lane + 32]) : 0.f;
    return warp_sum_f(n);
}

__global__ __launch_bounds__(RTPB) void k_route_spin(float* __restrict__ out) {
    __shared__ float ud[IC * OC];
    __shared__ float cc[IC * OC];
    __shared__ float redw[RTPB / 32];
    __shared__ unsigned ep_s;
    const int tid  = threadIdx.x;
    const int lane = tid & 31;
    const int w    = tid >> 5;
    const int t    = blockIdx.x * RTPB + tid;
    const int o    = t >> 10;

    if (tid == 0) ep_s = g_flag[blockIdx.x];

    for (int k = tid; k < IC * OC; k += RTPB)
        ud[k] = __ldcg(&g_udot_p[0][k]) + __ldcg(&g_udot_p[1][k]);

    float x[IC];
#pragma unroll
    for (int i = 0; i < IC; i++) x[i] = __ldcg(&g_usum_p[0][i * NT + t]);
#pragma unroll
    for (int i = 0; i < IC; i++) x[i] += __ldcg(&g_usum_p[1][i * NT + t]);
    __syncthreads();
    const unsigned ep = ep_s;

    float s1 = 0.f;
#pragma unroll
    for (int i = 0; i < IC; i++) s1 += x[i];
    s1 *= (1.f / 32.f);
    block_part_s(s1, redw, 0);
    gbar(ep + 1);

    {
        float n1 = read_norm_s(0);
        for (int oo = w; oo < OC; oo += RTPB / 32)
            cc[lane * OC + oo] = coupling_val(ud[lane * OC + oo], n1, 0.f, 2);
    }
    __syncthreads();
    float s2 = 0.f;
#pragma unroll
    for (int i = 0; i < IC; i++) s2 = fmaf(cc[i * OC + o], x[i], s2);
    block_part_s(s2, redw, 1);
    gbar(ep + 2);

    {
        float n1 = read_norm_s(0);
        float n2 = read_norm_s(1);
        for (int oo = w; oo < OC; oo += RTPB / 32)
            cc[lane * OC + oo] = coupling_val(ud[lane * OC + oo], n1, n2, 3);
    }
    __syncthreads();
    float s3 = 0.f;
#pragma unroll
    for (int i = 0; i < IC; i++) s3 = fmaf(cc[i * OC + o], x[i], s3);
    block_part_s(s3, redw, 2);
    gbar(ep + 3);

    float n3 = read_norm_s(2);
    float fsh = n3 / (1.f + n3 * n3);
    int b = (t >> 4) & 63, ch = t & 15;
    out[(b * OC + o) * CH + ch] = s3 * fsh;
}

// ---------------------------------------------------------------------------
extern "C" void kernel_launch(void* const* d_in, const int* in_sizes, int n_in,
                              void* d_out, int out_size) {
    const float* u = (const float*)d_in[0];   // [64,32,8,6,6]
    const float* W = (const float*)d_in[1];   // [32,8,6,6,10,16]
    float* out = (float*)d_out;               // [64,10,16]
    (void)in_sizes; (void)n_in; (void)out_size;

    k1_gemm<<<640, 128>>>(u, W);

    cudaError_t e = cudaFuncSetAttribute(
        k_route_c, cudaFuncAttributeNonPortableClusterSizeAllowed, 1);
    if (e == cudaSuccess) {
        k_route_c<<<CLN, CTPB>>>(out);
        if (cudaGetLastError() != cudaSuccess)
            k_route_spin<<<RBLK, RTPB>>>(out);
    } else {
        (void)cudaGetLastError();
        k_route_spin<<<RBLK, RTPB>>>(out);
    }
}

// round 16
// speedup vs baseline: 1.0125x; 1.0111x over previous
#include <cuda_runtime.h>
#include <cuda_fp16.h>
#include <cstdint>
#include <math.h>

// Problem constants
#define IC    32         // in capsules
#define DDIM  288        // ich*w*h
#define OC    10         // out capsules
#define CH    16         // out channels
#define BSZ   64         // batch
#define JDIM  160        // OC*CH
#define NT    10240      // BSZ*OC*CH
// cluster route config: 16 CTAs x 640 threads == NT
#define CLN   16
#define CTPB  640
// fallback spin route config
#define RBLK  40
#define RTPB  256

// Scratch (device globals: no allocation allowed)
__device__ __half g_usum_h[2][IC * NT];           // PLANAR fp16 d-half partials
__device__ float g_udot_p[2][IC * OC];            // d-half partials of u_dot (fp32)
__device__ __align__(128) float g_part[3][RBLK];  // partials (fallback path only)
__device__ volatile unsigned g_flag[RBLK];        // spin-barrier epochs (fallback)

// ---------------------------------------------------------------------------
// K1: partial GEMM (R12-exact tiling: 640 blocks x 128 threads, 64b x 16j x
// 144d FFMA tile). Stores u_sum partial as coalesced __half2 into its plane.
// ---------------------------------------------------------------------------
__global__ __launch_bounds__(128) void k1_gemm(const float* __restrict__ u,
                                               const float* __restrict__ W) {
    const int bid = blockIdx.x;
    const int dh  = bid & 1;
    const int o   = (bid >> 1) % 10;
    const int i   = bid / 20;
    const int j0  = o * 16;
    const int tid = threadIdx.x;
    const int tx  = tid & 7;
    const int ty  = tid >> 3;

    __shared__ float u_t[16][68];
    __shared__ float w_s[16][16];
    __shared__ float redw[4];

    float acc[4][2] = {};

    const float* ug = u + i * DDIM + dh * 144;
    const float* wg = W + (size_t)i * DDIM * JDIM + (size_t)(dh * 144) * JDIM + j0;

    float upf[8], wpf[2];
#pragma unroll
    for (int p = 0; p < 8; p++) { int e = tid + p * 128; upf[p] = ug[(e >> 4) * (IC * DDIM) + (e & 15)]; }
#pragma unroll
    for (int p = 0; p < 2; p++) { int e = tid + p * 128; wpf[p] = wg[(e >> 4) * JDIM + (e & 15)]; }

    for (int c = 0; c < 9; c++) {
        __syncthreads();
#pragma unroll
        for (int p = 0; p < 8; p++) { int e = tid + p * 128; u_t[e & 15][e >> 4] = upf[p]; }
#pragma unroll
        for (int p = 0; p < 2; p++) { int e = tid + p * 128; w_s[e >> 4][e & 15] = wpf[p]; }
        __syncthreads();
        if (c < 8) {
            const int d0 = (c + 1) * 16;
#pragma unroll
            for (int p = 0; p < 8; p++) { int e = tid + p * 128; upf[p] = ug[(e >> 4) * (IC * DDIM) + d0 + (e & 15)]; }
#pragma unroll
            for (int p = 0; p < 2; p++) { int e = tid + p * 128; wpf[p] = wg[(d0 + (e >> 4)) * JDIM + (e & 15)]; }
        }
#pragma unroll
        for (int dd = 0; dd < 16; dd++) {
            float4 uv = *(const float4*)&u_t[dd][ty * 4];
            float2 wv = *(const float2*)&w_s[dd][tx * 2];
            acc[0][0] = fmaf(uv.x, wv.x, acc[0][0]); acc[0][1] = fmaf(uv.x, wv.y, acc[0][1]);
            acc[1][0] = fmaf(uv.y, wv.x, acc[1][0]); acc[1][1] = fmaf(uv.y, wv.y, acc[1][1]);
            acc[2][0] = fmaf(uv.z, wv.x, acc[2][0]); acc[2][1] = fmaf(uv.z, wv.y, acc[2][1]);
            acc[3][0] = fmaf(uv.w, wv.x, acc[3][0]); acc[3][1] = fmaf(uv.w, wv.y, acc[3][1]);
        }
    }

    // coalesced __half2 store (the jj-pair is ch, ch+1 = adjacent halfs);
    // per-thread fp32 sum for u_dot
    float lsum = 0.f;
    __half2* dst2 = (__half2*)(g_usum_h[dh] + (size_t)i * NT + o * 1024);
#pragma unroll
    for (int bb = 0; bb < 4; bb++) {
        int b = ty * 4 + bb;
        dst2[b * 8 + tx] = __floats2half2_rn(acc[bb][0], acc[bb][1]);
        lsum += acc[bb][0] + acc[bb][1];
    }
#pragma unroll
    for (int off = 16; off > 0; off >>= 1) lsum += __shfl_xor_sync(0xffffffffu, lsum, off);
    if ((tid & 31) == 0) redw[tid >> 5] = lsum;
    __syncthreads();
    if (tid == 0) g_udot_p[dh][i * OC + o] = (redw[0] + redw[1]) + (redw[2] + redw[3]);
}

// ---------------------------------------------------------------------------
__device__ __forceinline__ float warp_sum_f(float v) {
#pragma unroll
    for (int o = 16; o > 0; o >>= 1) v += __shfl_xor_sync(0xffffffffu, v, o);
    return v;
}
__device__ __forceinline__ float warp_max_f(float v) {
#pragma unroll
    for (int o = 16; o > 0; o >>= 1) v = fmaxf(v, __shfl_xor_sync(0xffffffffu, v, o));
    return v;
}

// ===========================================================================
// Cluster route: 16 CTAs x 640 threads; warp-local coupling + shfl sweep;
// DSMEM partial exchange; split arrive/wait in phase 1 to hide xd/S1.
// x loaded as fp16 from two planar arrays (half the sectors of fp32).
// ===========================================================================
__device__ __forceinline__ unsigned int smem_u32(const void* p) {
    unsigned int a;
    asm("{ .reg .u64 t; cvta.to.shared.u64 t, %1; cvt.u32.u64 %0, t; }"
        : "=r"(a) : "l"(p));
    return a;
}

__device__ __forceinline__ void cluster_arrive_all() {
    asm volatile("barrier.cluster.arrive.aligned;" ::: "memory");
}
__device__ __forceinline__ void cluster_wait_all() {
    asm volatile("barrier.cluster.wait.aligned;" ::: "memory");
}

__device__ __forceinline__ void dsmem_store_rank(unsigned int laddr, int rank, float val) {
    asm volatile(
        "{ .reg .b32 ra; mapa.shared::cluster.u32 ra, %0, %1; "
        "st.shared::cluster.f32 [ra], %2; }"
        :: "r"(laddr), "r"(rank), "f"(val) : "memory");
}

__global__ __launch_bounds__(CTPB, 1) __cluster_dims__(CLN, 1, 1)
void k_route_c(float* __restrict__ out) {
    __shared__ float redw[CTPB / 32];
    __shared__ float part_s[3][CLN];
    const int tid  = threadIdx.x;
    const int lane = tid & 31;
    const int w    = tid >> 5;
    const int t    = blockIdx.x * CTPB + tid;
    const int o    = t >> 10;            // warp-uniform

    // ---- prologue: x[i] from two planar fp16 d-half buffers ----
    __half x0h[IC], x1h[IC];
#pragma unroll
    for (int i = 0; i < IC; i++) x0h[i] = __ldcg(&g_usum_h[0][i * NT + t]);
#pragma unroll
    for (int i = 0; i < IC; i++) x1h[i] = __ldcg(&g_usum_h[1][i * NT + t]);
    float x[IC];
#pragma unroll
    for (int i = 0; i < IC; i++) x[i] = __half2float(x0h[i]) + __half2float(x1h[i]);

    // ---- phase 1: publish s1 partial; hide xd load + S1 behind barrier ----
    float s1 = 0.f;
#pragma unroll
    for (int i = 0; i < IC; i++) s1 += x[i];
    s1 *= (1.f / 32.f);
    {
        float ws = warp_sum_f(fabsf(s1));
        if (lane == 0) redw[w] = ws;
        __syncthreads();
        if (w == 0) {
            float a = warp_sum_f((lane < CTPB / 32) ? redw[lane] : 0.f);
            if (lane < CLN)
                dsmem_store_rank(smem_u32(&part_s[0][blockIdx.x]), lane, a);
        }
        cluster_arrive_all();
    }
    float xd = __ldcg(&g_udot_p[0][lane * OC + o]) + __ldcg(&g_udot_p[1][lane * OC + o]);
    const float S1 = warp_sum_f(xd) * (1.f / 32.f);   // phase-invariant
    cluster_wait_all();

#define PHASE_PART(v, it)                                                     \
    {                                                                         \
        float ws = warp_sum_f(fabsf(v));                                      \
        if (lane == 0) redw[w] = ws;                                          \
        __syncthreads();                                                      \
        if (w == 0) {                                                         \
            float a = warp_sum_f((lane < CTPB / 32) ? redw[lane] : 0.f);      \
            if (lane < CLN)                                                   \
                dsmem_store_rank(smem_u32(&part_s[it][blockIdx.x]), lane, a); \
        }                                                                     \
        cluster_arrive_all();                                                 \
        cluster_wait_all();                                                   \
    }
#define READ_NORM(it)  warp_sum_f((lane < CLN) ? part_s[it][lane] : 0.f)

    // ---- phase 2: c2 = softmax_i(xd*g2), g2 = f1*S1 (shift-free, tiny logits)
    float n1 = READ_NORM(0);
    float f1 = n1 / (1.f + n1 * n1);
    float g2 = f1 * S1;
    float e2 = __expf(xd * g2);
    float c2 = e2 * (1.f / warp_sum_f(e2));
    float S2 = warp_sum_f(c2 * xd);
    float s2 = 0.f;
#pragma unroll
    for (int i = 0; i < IC; i++)
        s2 = fmaf(__shfl_sync(0xffffffffu, c2, i), x[i], s2);
    PHASE_PART(s2, 1);

    // ---- phase 3: c3 = softmax_i(xd*(g2 + f2*S2)) ----
    float n2 = READ_NORM(1);
    float f2 = n2 / (1.f + n2 * n2);
    float g3 = g2 + f2 * S2;
    float e3 = __expf(xd * g3);
    float c3 = e3 * (1.f / warp_sum_f(e3));
    float s3 = 0.f;
#pragma unroll
    for (int i = 0; i < IC; i++)
        s3 = fmaf(__shfl_sync(0xffffffffu, c3, i), x[i], s3);
    PHASE_PART(s3, 2);

    // ---- epilogue: squash scale + output ----
    float n3 = READ_NORM(2);
    float fsh = n3 / (1.f + n3 * n3);
    int b = (t >> 4) & 63, ch = t & 15;
    out[(b * OC + o) * CH + ch] = s3 * fsh;
#undef PHASE_PART
#undef READ_NORM
}

// ===========================================================================
// Fallback spin route (flag-array barrier), planar fp16 x.
// ===========================================================================
__device__ __forceinline__ float coupling_val(float xd, float n1, float n2, int iter) {
    float f1 = n1 / (1.f + n1 * n1);
    float S1 = warp_sum_f(xd) * (1.f / 32.f);
    float g = f1 * S1;
    if (iter == 3) {
        float bx = xd * g;
        float m = warp_max_f(bx);
        float e = expf(bx - m);
        float Z = warp_sum_f(e);
        float c2 = e / Z;
        float S2 = warp_sum_f(c2 * xd);
        float f2 = n2 / (1.f + n2 * n2);
        g = g + f2 * S2;
    }
    float bx = xd * g;
    float m = warp_max_f(bx);
    float e = expf(bx - m);
    float Z = warp_sum_f(e);
    return e / Z;
}

__device__ __forceinline__ void gbar(unsigned target) {
    __syncthreads();
    if (threadIdx.x < 32) {
        const int lane = threadIdx.x;
        if (lane == 0) {
            __threadfence();
            g_flag[blockIdx.x] = target;
        }
        bool done;
        do {
            unsigned f0 = g_flag[lane];
            unsigned f1 = (lane < RBLK - 32) ? g_flag[lane + 32] : target;
            done = __all_sync(0xffffffffu, (f0 == target) && (f1 == target));
        } while (!done);
        __threadfence();
    }
    __syncthreads();
}

__device__ __forceinline__ void block_part_s(float v, float* redw, int it) {
    float ws = warp_sum_f(fabsf(v));
    if ((threadIdx.x & 31) == 0) redw[threadIdx.x >> 5] = ws;
    __syncthreads();
    if (threadIdx.x == 0) {
        float a = 0.f;
#pragma unroll
        for (int k = 0; k < RTPB / 32; k++) a += redw[k];
        g_part[it][blockIdx.x] = a;
    }
}

__device__ __forceinline__ float read_norm_s(int it) {
    const int lane = threadIdx.x & 31;
    float n = __ldcg(&g_part[it][lane]);
    n += (lane < RBLK - 32) ? __ldcg(&g_part[it][lane + 32]) : 0.f;
    return warp_sum_f(n);
}

__global__ __launch_bounds__(RTPB) void k_route_spin(float* __restrict__ out) {
    __shared__ float ud[IC * OC];
    __shared__ float cc[IC * OC];
    __shared__ float redw[RTPB / 32];
    __shared__ unsigned ep_s;
    const int tid  = threadIdx.x;
    const int lane = tid & 31;
    const int w    = tid >> 5;
    const int t    = blockIdx.x * RTPB + tid;
    const int o    = t >> 10;

    if (tid == 0) ep_s = g_flag[blockIdx.x];

    for (int k = tid; k < IC * OC; k += RTPB)
        ud[k] = __ldcg(&g_udot_p[0][k]) + __ldcg(&g_udot_p[1][k]);

    float x[IC];
#pragma unroll
    for (int i = 0; i < IC; i++)
        x[i] = __half2float(__ldcg(&g_usum_h[0][i * NT + t]))
             + __half2float(__ldcg(&g_usum_h[1][i * NT + t]));
    __syncthreads();
    const unsigned ep = ep_s;

    float s1 = 0.f;
#pragma unroll
    for (int i = 0; i < IC; i++) s1 += x[i];
    s1 *= (1.f / 32.f);
    block_part_s(s1, redw, 0);
    gbar(ep + 1);

    {
        float n1 = read_norm_s(0);
        for (int oo = w; oo < OC; oo += RTPB / 32)
            cc[lane * OC + oo] = coupling_val(ud[lane * OC + oo], n1, 0.f, 2);
    }
    __syncthreads();
    float s2 = 0.f;
#pragma unroll
    for (int i = 0; i < IC; i++) s2 = fmaf(cc[i * OC + o], x[i], s2);
    block_part_s(s2, redw, 1);
    gbar(ep + 2);

    {
        float n1 = read_norm_s(0);
        float n2 = read_norm_s(1);
        for (int oo = w; oo < OC; oo += RTPB / 32)
            cc[lane * OC + oo] = coupling_val(ud[lane * OC + oo], n1, n2, 3);
    }
    __syncthreads();
    float s3 = 0.f;
#pragma unroll
    for (int i = 0; i < IC; i++) s3 = fmaf(cc[i * OC + o], x[i], s3);
    block_part_s(s3, redw, 2);
    gbar(ep + 3);

    float n3 = read_norm_s(2);
    float fsh = n3 / (1.f + n3 * n3);
    int b = (t >> 4) & 63, ch = t & 15;
    out[(b * OC + o) * CH + ch] = s3 * fsh;
}

// ---------------------------------------------------------------------------
extern "C" void kernel_launch(void* const* d_in, const int* in_sizes, int n_in,
                              void* d_out, int out_size) {
    const float* u = (const float*)d_in[0];   // [64,32,8,6,6]
    const float* W = (const float*)d_in[1];   // [32,8,6,6,10,16]
    float* out = (float*)d_out;               // [64,10,16]
    (void)in_sizes; (void)n_in; (void)out_size;

    k1_gemm<<<640, 128>>>(u, W);

    cudaError_t e = cudaFuncSetAttribute(
        k_route_c, cudaFuncAttributeNonPortableClusterSizeAllowed, 1);
    if (e == cudaSuccess) {
        k_route_c<<<CLN, CTPB>>>(out);
        if (cudaGetLastError() != cudaSuccess)
            k_route_spin<<<RBLK, RTPB>>>(out);
    } else {
        (void)cudaGetLastError();
        k_route_spin<<<RBLK, RTPB>>>(out);
    }
}